// round 8
// baseline (speedup 1.0000x reference)
#include <cuda_runtime.h>
#include <cuda_bf16.h>
#include <cstdint>

namespace {
constexpr int kB   = 16;
constexpr int kM   = 512;
constexpr int kRows = kB * 512;  // 8192
}

// ---------------- scratch (device globals; no allocation) -------------------
__device__ __align__(16) __nv_bfloat16 g_w1b[512 * 128];       // w1 bf16
__device__ __align__(16) __nv_bfloat16 g_wTt[2 * 256 * 256];   // wT^T bf16 [g][co2][i]
__device__ __align__(16) __nv_bfloat16 g_hp[kRows * 1024];     // pooled hidden bf16
__device__ __align__(16) __nv_bfloat16 g_scb[kRows * 512];     // scores bf16
__device__ __align__(16) __nv_bfloat16 g_at[kRows * 512];      // attn bf16
__device__ __align__(16) __nv_bfloat16 g_hrT[kB * 1024 * 512]; // retrieved^T bf16
__device__ __align__(16) __nv_bfloat16 g_pat[512 * 1024];      // patterns bf16 [m][lp]

// ---------------- PTX helpers ------------------------------------------------
__device__ __forceinline__ void cp_async16(uint32_t dst, const void* src) {
  asm volatile("cp.async.cg.shared.global [%0], [%1], 16;\n" ::"r"(dst), "l"(src));
}
#define CP_COMMIT() asm volatile("cp.async.commit_group;\n" ::: "memory")
#define CP_WAIT(n) asm volatile("cp.async.wait_group %0;\n" ::"n"(n) : "memory")

__device__ __forceinline__ void ldsm_x4(uint32_t (&r)[4], uint32_t addr) {
  asm volatile(
      "ldmatrix.sync.aligned.m8n8.x4.shared.b16 {%0,%1,%2,%3}, [%4];"
      : "=r"(r[0]), "=r"(r[1]), "=r"(r[2]), "=r"(r[3])
      : "r"(addr));
}
__device__ __forceinline__ void ldsm_x4_t(uint32_t (&r)[4], uint32_t addr) {
  asm volatile(
      "ldmatrix.sync.aligned.m8n8.x4.trans.shared.b16 {%0,%1,%2,%3}, [%4];"
      : "=r"(r[0]), "=r"(r[1]), "=r"(r[2]), "=r"(r[3])
      : "r"(addr));
}

__device__ __forceinline__ void mma_16816(float (&c)[4], const uint32_t (&a)[4],
                                          const uint32_t b0, const uint32_t b1) {
  asm volatile(
      "mma.sync.aligned.m16n8k16.row.col.f32.bf16.bf16.f32 "
      "{%0,%1,%2,%3}, {%4,%5,%6,%7}, {%8,%9}, {%0,%1,%2,%3};"
      : "+f"(c[0]), "+f"(c[1]), "+f"(c[2]), "+f"(c[3])
      : "r"(a[0]), "r"(a[1]), "r"(a[2]), "r"(a[3]), "r"(b0), "r"(b1));
}

__device__ __forceinline__ uint32_t pack_bf16(float a, float b) {
  __nv_bfloat162 p = __floats2bfloat162_rn(a, b);
  return *(uint32_t*)&p;
}

__device__ __forceinline__ void cvt_store16(char* d, const float4 (&v)[4]) {
  uint4 q0, q1;
  q0.x = pack_bf16(v[0].x, v[0].y); q0.y = pack_bf16(v[0].z, v[0].w);
  q0.z = pack_bf16(v[1].x, v[1].y); q0.w = pack_bf16(v[1].z, v[1].w);
  q1.x = pack_bf16(v[2].x, v[2].y); q1.y = pack_bf16(v[2].z, v[2].w);
  q1.z = pack_bf16(v[3].x, v[3].y); q1.w = pack_bf16(v[3].z, v[3].w);
  *(uint4*)d = q0;
  *((uint4*)d + 1) = q1;
}

// ---------------------------------------------------------------------------
// Prep: w1 -> g_w1b, wT -> g_wTt (transposed), pat -> g_pat
// ---------------------------------------------------------------------------
__global__ __launch_bounds__(256) void kprep_all(const float* __restrict__ w1,
                                                 const float* __restrict__ wT,
                                                 const float* __restrict__ pat) {
  const int bid = blockIdx.x;
  const int t = threadIdx.x;
  if (bid < 64) {
    const int idx = (bid * 256 + t) * 4;
    const float4 v = *(const float4*)(w1 + idx);
    uint2 o;
    o.x = pack_bf16(v.x, v.y);
    o.y = pack_bf16(v.z, v.w);
    *(uint2*)&g_w1b[idx] = o;
  } else if (bid < 576) {
    const int idx = (bid - 64) * 256 + t;
    const int g = idx >> 16, co2 = (idx >> 8) & 255, i = idx & 255;
    g_wTt[idx] = __float2bfloat16(wT[(size_t)(g * 256 + i) * 256 + co2]);
  } else {
    const int idx = ((bid - 576) * 256 + t) * 4;
    const float4 v = *(const float4*)(pat + idx);
    uint2 o;
    o.x = pack_bf16(v.x, v.y);
    o.y = pack_bf16(v.z, v.w);
    *(uint2*)&g_pat[idx] = o;
  }
}

// ---------------------------------------------------------------------------
// k1: HMMA grouped 1x1 conv + bias + ReLU + maxpool2 -> g_hp bf16 (r7 version)
// ---------------------------------------------------------------------------
__global__ __launch_bounds__(256) void k1_hmma(const float* __restrict__ x,
                                               const float* __restrict__ b1) {
  __shared__ __align__(16) char smem[37888];
  const int t = threadIdx.x, w = t >> 5, lid = t & 31;
  const int wm = w >> 2, wn = w & 3;
  const int bx = blockIdx.x, by = blockIdx.y, bz = blockIdx.z;
  const int b = bz >> 1, g = bz & 1;
  const uint32_t sAb = (uint32_t)__cvta_generic_to_shared(smem);
  const char* Ag = (const char*)(g_w1b + (size_t)(g * 256 + by * 128) * 128);
  const float* xB = x + ((size_t)(b * 256 + g * 128)) * 2048 + bx * 128;

  const int brow = t >> 3, bcq = t & 7;
  const float* xrow = xB + (size_t)brow * 2048 + bcq * 16;

  auto ldA = [&](int s, int it) {
#pragma unroll
    for (int i = 0; i < 2; ++i) {
      const int idx = t + i * 256;
      const int row = idx >> 2, ch = idx & 3;
      cp_async16(sAb + s * 10240 + row * 80 + ch * 16,
                 Ag + row * 256 + it * 64 + ch * 16);
    }
    CP_COMMIT();
  };

  float4 v[4];
  auto ldB = [&](int it) {
    const float4* p = (const float4*)(xrow + (size_t)it * 32 * 2048);
#pragma unroll
    for (int q = 0; q < 4; ++q) v[q] = p[q];
  };
  auto stB = [&](int s) {
    cvt_store16(smem + 20480 + s * 8704 + brow * 272 + bcq * 32, v);
  };

  float acc[4][4][4];
#pragma unroll
  for (int mt = 0; mt < 4; ++mt)
#pragma unroll
    for (int nt = 0; nt < 4; ++nt)
#pragma unroll
      for (int i = 0; i < 4; ++i) acc[mt][nt][i] = 0.f;

  ldA(0, 0);
  ldB(0);
  const uint32_t aAddr0 = sAb + (wm * 64 + (lid & 15)) * 80 + (lid >> 4) * 16;
  const uint32_t bAddr0 = sAb + 20480 +
      (((lid >> 3) & 1) * 8 + (lid & 7)) * 272 + (wn * 32 + (lid >> 4) * 8) * 2;

#pragma unroll 1
  for (int it = 0; it < 4; ++it) {
    if (it + 1 < 4) {
      ldA((it + 1) & 1, it + 1);
      CP_WAIT(1);
    } else {
      CP_WAIT(0);
    }
    stB(it & 1);
    __syncthreads();
    if (it + 1 < 4) ldB(it + 1);
    const uint32_t sOA = (uint32_t)(it & 1) * 10240;
    const uint32_t sOB = (uint32_t)(it & 1) * 8704;
#pragma unroll
    for (int ks = 0; ks < 2; ++ks) {
      uint32_t afr[4][4];
      uint32_t bfr[4][2];
#pragma unroll
      for (int mt = 0; mt < 4; ++mt)
        ldsm_x4(afr[mt], aAddr0 + sOA + mt * 16 * 80 + ks * 32);
#pragma unroll
      for (int nt2 = 0; nt2 < 2; ++nt2) {
        uint32_t r4[4];
        ldsm_x4_t(r4, bAddr0 + sOB + ks * 16 * 272 + nt2 * 32);
        bfr[nt2 * 2 + 0][0] = r4[0]; bfr[nt2 * 2 + 0][1] = r4[1];
        bfr[nt2 * 2 + 1][0] = r4[2]; bfr[nt2 * 2 + 1][1] = r4[3];
      }
#pragma unroll
      for (int mt = 0; mt < 4; ++mt)
#pragma unroll
        for (int nt = 0; nt < 4; ++nt)
          mma_16816(acc[mt][nt], afr[mt], bfr[nt][0], bfr[nt][1]);
    }
    __syncthreads();
  }

  __nv_bfloat16* sH = (__nv_bfloat16*)smem;  // [128][72]
#pragma unroll
  for (int mt = 0; mt < 4; ++mt) {
    const int m = wm * 64 + mt * 16 + (lid >> 2);
    const int og = g * 256 + by * 128 + m;
    const float bias0 = b1[og];
    const float bias1 = b1[og + 8];
#pragma unroll
    for (int nt = 0; nt < 4; ++nt) {
      const int np = wn * 16 + nt * 4 + (lid & 3);
      sH[m * 72 + np] =
          __float2bfloat16(fmaxf(fmaxf(acc[mt][nt][0], acc[mt][nt][1]) + bias0, 0.f));
      sH[(m + 8) * 72 + np] =
          __float2bfloat16(fmaxf(fmaxf(acc[mt][nt][2], acc[mt][nt][3]) + bias1, 0.f));
    }
  }
  __syncthreads();
  const size_t rowbase = (size_t)(b * 512 + g * 256 + by * 128);
  const int colbase = bx * 64;
#pragma unroll
  for (int p = 0; p < 4; ++p) {
    const int idx = t + p * 256;
    const int row = idx >> 3, ch = idx & 7;
    *(uint4*)&g_hp[(rowbase + row) * 1024 + colbase + ch * 8] =
        *(uint4*)&sH[row * 72 + ch * 8];
  }
}

// ---------------------------------------------------------------------------
// k2: scores = Hp @ P^T (K=1024), block 128x256, warp 64x64, 3-stage.
// grid (2, 64) = 128 CTAs. dyn smem 92160.
// ---------------------------------------------------------------------------
__global__ __launch_bounds__(256) void kgemm_scores() {
  constexpr int ITERS = 32;
  extern __shared__ __align__(16) char smem[];  // A 3x10240 | B 3x20480
  const int t = threadIdx.x, w = t >> 5, lid = t & 31;
  const int wm = w >> 2, wn = w & 3;
  const int n0 = blockIdx.x * 256;
  const int r0 = blockIdx.y * 128;
  const uint32_t sAb = (uint32_t)__cvta_generic_to_shared(smem);
  constexpr uint32_t BOFF = 30720;
  const char* Ab = (const char*)(g_hp + (size_t)r0 * 1024);
  const char* Bb = (const char*)(g_pat + (size_t)n0 * 1024);

  auto load_tile = [&](int s, int it) {
#pragma unroll
    for (int i = 0; i < 2; ++i) {  // A: 128 rows x 64B
      const int idx = t + i * 256;
      const int row = idx >> 2, ch = idx & 3;
      cp_async16(sAb + s * 10240 + row * 80 + ch * 16,
                 Ab + (size_t)row * 2048 + it * 64 + ch * 16);
    }
#pragma unroll
    for (int i = 0; i < 4; ++i) {  // B: 256 rows x 64B
      const int idx = t + i * 256;
      const int row = idx >> 2, ch = idx & 3;
      cp_async16(sAb + BOFF + s * 20480 + row * 80 + ch * 16,
                 Bb + (size_t)row * 2048 + it * 64 + ch * 16);
    }
    CP_COMMIT();
  };

  float acc[4][8][4];
#pragma unroll
  for (int mt = 0; mt < 4; ++mt)
#pragma unroll
    for (int nt = 0; nt < 8; ++nt)
#pragma unroll
      for (int i = 0; i < 4; ++i) acc[mt][nt][i] = 0.f;

  load_tile(0, 0);
  load_tile(1, 1);
  const uint32_t aAddr0 = sAb + (wm * 64 + (lid & 15)) * 80 + (lid >> 4) * 16;
  const uint32_t bAddr0 = sAb + BOFF +
      (wn * 64 + ((lid >> 4) ? 8 : 0) + (lid & 7)) * 80 + ((lid >> 3) & 1) * 16;

  int s3 = 0;
#pragma unroll 1
  for (int it = 0; it < ITERS; ++it) {
    if (it + 1 < ITERS) { CP_WAIT(1); } else { CP_WAIT(0); }
    __syncthreads();
    int nx = s3 + 2; if (nx >= 3) nx -= 3;
    if (it + 2 < ITERS) load_tile(nx, it + 2);
    const uint32_t sOA = (uint32_t)s3 * 10240;
    const uint32_t sOB = (uint32_t)s3 * 20480;
#pragma unroll
    for (int ks = 0; ks < 2; ++ks) {
      uint32_t afr[4][4];
#pragma unroll
      for (int mt = 0; mt < 4; ++mt)
        ldsm_x4(afr[mt], aAddr0 + sOA + mt * 16 * 80 + ks * 32);
#pragma unroll
      for (int nt2 = 0; nt2 < 4; ++nt2) {
        uint32_t r4[4];
        ldsm_x4(r4, bAddr0 + sOB + nt2 * 16 * 80 + ks * 32);
#pragma unroll
        for (int mt = 0; mt < 4; ++mt) {
          mma_16816(acc[mt][nt2 * 2 + 0], afr[mt], r4[0], r4[1]);
          mma_16816(acc[mt][nt2 * 2 + 1], afr[mt], r4[2], r4[3]);
        }
      }
    }
    s3 = (s3 + 1 == 3) ? 0 : s3 + 1;
  }

  __nv_bfloat16* Crow = g_scb + (size_t)(r0 + wm * 64) * 512 + n0 + wn * 64;
  const int rr = lid >> 2;
  const int cc = (lid & 3) * 2;
#pragma unroll
  for (int mt = 0; mt < 4; ++mt)
#pragma unroll
    for (int nt = 0; nt < 8; ++nt) {
      *(uint32_t*)&Crow[(size_t)(mt * 16 + rr) * 512 + nt * 8 + cc] =
          pack_bf16(acc[mt][nt][0], acc[mt][nt][1]);
      *(uint32_t*)&Crow[(size_t)(mt * 16 + rr + 8) * 512 + nt * 8 + cc] =
          pack_bf16(acc[mt][nt][2], acc[mt][nt][3]);
    }
}

// ---------------------------------------------------------------------------
// k3: softmax over m=512 — warp per row, bf16 in/out
// ---------------------------------------------------------------------------
__global__ __launch_bounds__(256) void k3_softmax() {
  const int wid = threadIdx.x >> 5, lane = threadIdx.x & 31;
  const size_t row = (size_t)blockIdx.x * 8 + wid;
  const uint4* rp = (const uint4*)(g_scb + row * 512);
  const uint4 q0 = rp[lane];
  const uint4 q1 = rp[lane + 32];

  float f[16];
  {
    const uint32_t us[8] = {q0.x, q0.y, q0.z, q0.w, q1.x, q1.y, q1.z, q1.w};
#pragma unroll
    for (int i = 0; i < 8; ++i) {
      const __nv_bfloat162 p = *(const __nv_bfloat162*)&us[i];
      f[2 * i] = __bfloat162float(p.x);
      f[2 * i + 1] = __bfloat162float(p.y);
    }
  }
  float m = f[0];
#pragma unroll
  for (int i = 1; i < 16; ++i) m = fmaxf(m, f[i]);
#pragma unroll
  for (int o = 16; o; o >>= 1) m = fmaxf(m, __shfl_xor_sync(0xffffffffu, m, o));
  float s = 0.f;
#pragma unroll
  for (int i = 0; i < 16; ++i) {
    f[i] = __expf(f[i] - m);
    s += f[i];
  }
#pragma unroll
  for (int o = 16; o; o >>= 1) s += __shfl_xor_sync(0xffffffffu, s, o);
  const float inv = 1.f / s;

  uint4 o0, o1;
  o0.x = pack_bf16(f[0] * inv, f[1] * inv);
  o0.y = pack_bf16(f[2] * inv, f[3] * inv);
  o0.z = pack_bf16(f[4] * inv, f[5] * inv);
  o0.w = pack_bf16(f[6] * inv, f[7] * inv);
  o1.x = pack_bf16(f[8] * inv, f[9] * inv);
  o1.y = pack_bf16(f[10] * inv, f[11] * inv);
  o1.z = pack_bf16(f[12] * inv, f[13] * inv);
  o1.w = pack_bf16(f[14] * inv, f[15] * inv);
  uint4* op = (uint4*)(g_at + row * 512);
  op[lane] = o0;
  op[lane + 32] = o1;
}

// ---------------------------------------------------------------------------
// k4: retrieval = Attn @ P (K=512), block 128x256 (lp), warp 64x64,
// B trans-ldmatrix from g_pat. grid (4, 64) = 256 CTAs. dyn smem 81408.
// Epilogue -> g_hrT transposed.
// ---------------------------------------------------------------------------
__global__ __launch_bounds__(256) void kgemm_retrieve() {
  constexpr int ITERS = 16;
  extern __shared__ __align__(16) char smem[];  // A 3x10240 | B 3x16896
  const int t = threadIdx.x, w = t >> 5, lid = t & 31;
  const int wm = w >> 2, wn = w & 3;
  const int n0 = blockIdx.x * 256;  // lp
  const int r0 = blockIdx.y * 128;  // attn row
  const uint32_t sAb = (uint32_t)__cvta_generic_to_shared(smem);
  constexpr uint32_t BOFF = 30720;
  const char* Ab = (const char*)(g_at + (size_t)r0 * 512);
  const char* Bb = (const char*)(g_pat + n0);

  auto load_tile = [&](int s, int it) {
#pragma unroll
    for (int i = 0; i < 2; ++i) {  // A: 128 rows x 64B
      const int idx = t + i * 256;
      const int row = idx >> 2, ch = idx & 3;
      cp_async16(sAb + s * 10240 + row * 80 + ch * 16,
                 Ab + (size_t)row * 1024 + it * 64 + ch * 16);
    }
#pragma unroll
    for (int i = 0; i < 4; ++i) {  // B: 32 m-rows x 512B
      const int idx = t + i * 256;
      const int row = idx >> 5, ch = idx & 31;
      cp_async16(sAb + BOFF + s * 16896 + row * 528 + ch * 16,
                 Bb + (size_t)(it * 32 + row) * 2048 + ch * 16);
    }
    CP_COMMIT();
  };

  float acc[4][8][4];
#pragma unroll
  for (int mt = 0; mt < 4; ++mt)
#pragma unroll
    for (int nt = 0; nt < 8; ++nt)
#pragma unroll
      for (int i = 0; i < 4; ++i) acc[mt][nt][i] = 0.f;

  load_tile(0, 0);
  load_tile(1, 1);
  const uint32_t aAddr0 = sAb + (wm * 64 + (lid & 15)) * 80 + (lid >> 4) * 16;
  const uint32_t bAddr0 = sAb + BOFF +
      (((lid >> 3) & 1) * 8 + (lid & 7)) * 528 + (wn * 64 + (lid >> 4) * 8) * 2;

  int s3 = 0;
#pragma unroll 1
  for (int it = 0; it < ITERS; ++it) {
    if (it + 1 < ITERS) { CP_WAIT(1); } else { CP_WAIT(0); }
    __syncthreads();
    int nx = s3 + 2; if (nx >= 3) nx -= 3;
    if (it + 2 < ITERS) load_tile(nx, it + 2);
    const uint32_t sOA = (uint32_t)s3 * 10240;
    const uint32_t sOB = (uint32_t)s3 * 16896;
#pragma unroll
    for (int ks = 0; ks < 2; ++ks) {
      uint32_t afr[4][4];
#pragma unroll
      for (int mt = 0; mt < 4; ++mt)
        ldsm_x4(afr[mt], aAddr0 + sOA + mt * 16 * 80 + ks * 32);
#pragma unroll
      for (int nt2 = 0; nt2 < 4; ++nt2) {
        uint32_t r4[4];
        ldsm_x4_t(r4, bAddr0 + sOB + ks * 16 * 528 + nt2 * 32);
#pragma unroll
        for (int mt = 0; mt < 4; ++mt) {
          mma_16816(acc[mt][nt2 * 2 + 0], afr[mt], r4[0], r4[1]);
          mma_16816(acc[mt][nt2 * 2 + 1], afr[mt], r4[2], r4[3]);
        }
      }
    }
    s3 = (s3 + 1 == 3) ? 0 : s3 + 1;
  }
  __syncthreads();

  // transposed bf16 epilogue: stage [lp 256][c 128 pad 136]
  __nv_bfloat16* sT = (__nv_bfloat16*)smem;
#pragma unroll
  for (int mt = 0; mt < 4; ++mt) {
    const int m = wm * 64 + mt * 16 + (lid >> 2);
#pragma unroll
    for (int nt = 0; nt < 8; ++nt) {
      const int n = wn * 64 + nt * 8 + (lid & 3) * 2;
      sT[n * 136 + m] = __float2bfloat16(acc[mt][nt][0]);
      sT[(n + 1) * 136 + m] = __float2bfloat16(acc[mt][nt][1]);
      sT[n * 136 + m + 8] = __float2bfloat16(acc[mt][nt][2]);
      sT[(n + 1) * 136 + m + 8] = __float2bfloat16(acc[mt][nt][3]);
    }
  }
  __syncthreads();
  const int b = r0 >> 9;
  const int c0b = r0 & 511;
#pragma unroll
  for (int p = 0; p < 16; ++p) {
    const int idx = t + p * 256;
    const int row = idx >> 4, ch = idx & 15;
    *(uint4*)&g_hrT[((size_t)b * 1024 + n0 + row) * 512 + c0b + ch * 8] =
        *(uint4*)&sT[row * 136 + ch * 8];
  }
}

// ---------------------------------------------------------------------------
// k5: grouped ConvT(k=2,s=2) + bias + ReLU + residual.
// block: 128 lp x 256 co2 (ALL outputs of the group), K=256. warp 64x64.
// grid (8 lp, 32 bg) = 256 CTAs. dyn smem 92160.
// ---------------------------------------------------------------------------
__global__ __launch_bounds__(256) void k5_hmma(
    const float* __restrict__ x, const float* __restrict__ bT,
    const float* __restrict__ rzp, float* __restrict__ out) {
  constexpr int ITERS = 8;
  extern __shared__ __align__(16) char smem[];  // A 3x10240 | B 3x20480
  const int t = threadIdx.x, w = t >> 5, lid = t & 31;
  const int wm = w >> 2, wn = w & 3;
  const int by = blockIdx.x, bz = blockIdx.y;
  const int b = bz >> 1, g = bz & 1;
  const uint32_t sAb = (uint32_t)__cvta_generic_to_shared(smem);
  constexpr uint32_t BOFF = 30720;
  const char* Ab =
      (const char*)(g_hrT + ((size_t)b * 1024 + by * 128) * 512 + g * 256);
  const char* Bb = (const char*)(g_wTt + (size_t)g * 65536);

  auto load_tile = [&](int s, int it) {
#pragma unroll
    for (int i = 0; i < 2; ++i) {  // A: 128 rows x 64B
      const int idx = t + i * 256;
      const int row = idx >> 2, ch = idx & 3;
      cp_async16(sAb + s * 10240 + row * 80 + ch * 16,
                 Ab + (size_t)row * 1024 + it * 64 + ch * 16);
    }
#pragma unroll
    for (int i = 0; i < 4; ++i) {  // B: 256 rows x 64B
      const int idx = t + i * 256;
      const int row = idx >> 2, ch = idx & 3;
      cp_async16(sAb + BOFF + s * 20480 + row * 80 + ch * 16,
                 Bb + (size_t)row * 512 + it * 64 + ch * 16);
    }
    CP_COMMIT();
  };

  float acc[4][8][4];
#pragma unroll
  for (int mt = 0; mt < 4; ++mt)
#pragma unroll
    for (int nt = 0; nt < 8; ++nt)
#pragma unroll
      for (int i = 0; i < 4; ++i) acc[mt][nt][i] = 0.f;

  load_tile(0, 0);
  load_tile(1, 1);
  const uint32_t aAddr0 = sAb + (wm * 64 + (lid & 15)) * 80 + (lid >> 4) * 16;
  const uint32_t bAddr0 = sAb + BOFF +
      (wn * 64 + ((lid >> 4) ? 8 : 0) + (lid & 7)) * 80 + ((lid >> 3) & 1) * 16;

  int s3 = 0;
#pragma unroll 1
  for (int it = 0; it < ITERS; ++it) {
    if (it + 1 < ITERS) { CP_WAIT(1); } else { CP_WAIT(0); }
    __syncthreads();
    int nx = s3 + 2; if (nx >= 3) nx -= 3;
    if (it + 2 < ITERS) load_tile(nx, it + 2);
    const uint32_t sOA = (uint32_t)s3 * 10240;
    const uint32_t sOB = (uint32_t)s3 * 20480;
#pragma unroll
    for (int ks = 0; ks < 2; ++ks) {
      uint32_t afr[4][4];
#pragma unroll
      for (int mt = 0; mt < 4; ++mt)
        ldsm_x4(afr[mt], aAddr0 + sOA + mt * 16 * 80 + ks * 32);
#pragma unroll
      for (int nt2 = 0; nt2 < 4; ++nt2) {
        uint32_t r4[4];
        ldsm_x4(r4, bAddr0 + sOB + nt2 * 16 * 80 + ks * 32);
#pragma unroll
        for (int mt = 0; mt < 4; ++mt) {
          mma_16816(acc[mt][nt2 * 2 + 0], afr[mt], r4[0], r4[1]);
          mma_16816(acc[mt][nt2 * 2 + 1], afr[mt], r4[2], r4[3]);
        }
      }
    }
    s3 = (s3 + 1 == 3) ? 0 : s3 + 1;
  }
  __syncthreads();

  // epilogue: bias + relu -> bf16 stage y[co 128][l 264]; residual write
  __nv_bfloat16* sY = (__nv_bfloat16*)smem;
  float biasv[8];
#pragma unroll
  for (int nt = 0; nt < 8; ++nt) {
    const int co_l = wn * 32 + nt * 4 + (lid & 3);
    biasv[nt] = bT[g * 128 + co_l];
  }
#pragma unroll
  for (int mt = 0; mt < 4; ++mt) {
    const int m = wm * 64 + mt * 16 + (lid >> 2);
#pragma unroll
    for (int nt = 0; nt < 8; ++nt) {
      const int co_l = wn * 32 + nt * 4 + (lid & 3);
      __nv_bfloat162 p0 = __floats2bfloat162_rn(
          fmaxf(acc[mt][nt][0] + biasv[nt], 0.f),
          fmaxf(acc[mt][nt][1] + biasv[nt], 0.f));
      __nv_bfloat162 p1 = __floats2bfloat162_rn(
          fmaxf(acc[mt][nt][2] + biasv[nt], 0.f),
          fmaxf(acc[mt][nt][3] + biasv[nt], 0.f));
      *(__nv_bfloat162*)&sY[co_l * 264 + 2 * m] = p0;
      *(__nv_bfloat162*)&sY[co_l * 264 + 2 * m + 16] = p1;
    }
  }
  __syncthreads();
  const float rz = rzp[0];
  const int co_r = t >> 1;
  const int colseg = (t & 1) * 128;
  const int cog = g * 128 + co_r;
  const size_t rowoff = ((size_t)b * 256 + cog) * 2048 + by * 256;
#pragma unroll
  for (int j = 0; j < 8; ++j) {
    const int col = colseg + j * 16;
    const uint32_t* yp = (const uint32_t*)&sY[co_r * 264 + col];
#pragma unroll
    for (int q = 0; q < 4; ++q) {
      __nv_bfloat162 y0 = *(const __nv_bfloat162*)&yp[q * 2];
      __nv_bfloat162 y1 = *(const __nv_bfloat162*)&yp[q * 2 + 1];
      const float4 xv = *(const float4*)(x + rowoff + col + q * 4);
      float4 o4;
      o4.x = xv.x + rz * __bfloat162float(y0.x);
      o4.y = xv.y + rz * __bfloat162float(y0.y);
      o4.z = xv.z + rz * __bfloat162float(y1.x);
      o4.w = xv.w + rz * __bfloat162float(y1.y);
      *(float4*)(out + rowoff + col + q * 4) = o4;
    }
  }
}

// ---------------------------------------------------------------------------
extern "C" void kernel_launch(void* const* d_in, const int* in_sizes, int n_in,
                              void* d_out, int out_size) {
  (void)in_sizes; (void)n_in; (void)out_size;
  const float* x        = (const float*)d_in[0];
  const float* w1       = (const float*)d_in[1];
  const float* b1       = (const float*)d_in[2];
  const float* patterns = (const float*)d_in[3];
  const float* wT       = (const float*)d_in[4];
  const float* bT       = (const float*)d_in[5];
  const float* RZ       = (const float*)d_in[6];
  float* out            = (float*)d_out;

  cudaFuncSetAttribute(kgemm_scores,
                       cudaFuncAttributeMaxDynamicSharedMemorySize, 92160);
  cudaFuncSetAttribute(kgemm_retrieve,
                       cudaFuncAttributeMaxDynamicSharedMemorySize, 81408);
  cudaFuncSetAttribute(k5_hmma,
                       cudaFuncAttributeMaxDynamicSharedMemorySize, 92160);

  kprep_all<<<1088, 256>>>(w1, wT, patterns);
  k1_hmma<<<dim3(16, 2, 32), 256>>>(x, b1);
  kgemm_scores<<<dim3(2, 64), 256, 92160>>>();
  k3_softmax<<<kRows / 8, 256>>>();
  kgemm_retrieve<<<dim3(4, 64), 256, 81408>>>();
  k5_hmma<<<dim3(8, 32), 256, 92160>>>(x, bT, RZ, out);
}

// round 9
// speedup vs baseline: 1.1322x; 1.1322x over previous
#include <cuda_runtime.h>
#include <cuda_bf16.h>
#include <cstdint>

namespace {
constexpr int kB   = 16;
constexpr int kRows = kB * 512;  // 8192
}

// ---------------- scratch (device globals; no allocation) -------------------
__device__ __align__(16) __nv_bfloat16 g_w1b[512 * 128];       // w1 bf16
__device__ __align__(16) __nv_bfloat16 g_wTt[2 * 256 * 256];   // wT^T bf16 [g][co2][i]
__device__ __align__(16) __nv_bfloat16 g_hp[kRows * 1024];     // pooled hidden bf16
__device__ __align__(16) __nv_bfloat16 g_scb[kRows * 512];     // scores bf16
__device__ __align__(16) __nv_bfloat16 g_at[kRows * 512];      // attn bf16
__device__ __align__(16) __nv_bfloat16 g_hrT[kB * 1024 * 512]; // retrieved^T bf16
__device__ __align__(16) __nv_bfloat16 g_pat[512 * 1024];      // patterns bf16 [m][lp]

// ---------------- PTX helpers ------------------------------------------------
__device__ __forceinline__ void cp_async16(uint32_t dst, const void* src) {
  asm volatile("cp.async.cg.shared.global [%0], [%1], 16;\n" ::"r"(dst), "l"(src));
}
#define CP_COMMIT() asm volatile("cp.async.commit_group;\n" ::: "memory")
#define CP_WAIT(n) asm volatile("cp.async.wait_group %0;\n" ::"n"(n) : "memory")

__device__ __forceinline__ void ldsm_x4(uint32_t (&r)[4], uint32_t addr) {
  asm volatile(
      "ldmatrix.sync.aligned.m8n8.x4.shared.b16 {%0,%1,%2,%3}, [%4];"
      : "=r"(r[0]), "=r"(r[1]), "=r"(r[2]), "=r"(r[3])
      : "r"(addr));
}
__device__ __forceinline__ void ldsm_x4_t(uint32_t (&r)[4], uint32_t addr) {
  asm volatile(
      "ldmatrix.sync.aligned.m8n8.x4.trans.shared.b16 {%0,%1,%2,%3}, [%4];"
      : "=r"(r[0]), "=r"(r[1]), "=r"(r[2]), "=r"(r[3])
      : "r"(addr));
}

__device__ __forceinline__ void mma_16816(float (&c)[4], const uint32_t (&a)[4],
                                          const uint32_t b0, const uint32_t b1) {
  asm volatile(
      "mma.sync.aligned.m16n8k16.row.col.f32.bf16.bf16.f32 "
      "{%0,%1,%2,%3}, {%4,%5,%6,%7}, {%8,%9}, {%0,%1,%2,%3};"
      : "+f"(c[0]), "+f"(c[1]), "+f"(c[2]), "+f"(c[3])
      : "r"(a[0]), "r"(a[1]), "r"(a[2]), "r"(a[3]), "r"(b0), "r"(b1));
}

__device__ __forceinline__ uint32_t pack_bf16(float a, float b) {
  __nv_bfloat162 p = __floats2bfloat162_rn(a, b);
  return *(uint32_t*)&p;
}

__device__ __forceinline__ void cvt_store16(char* d, const float4 (&v)[4]) {
  uint4 q0, q1;
  q0.x = pack_bf16(v[0].x, v[0].y); q0.y = pack_bf16(v[0].z, v[0].w);
  q0.z = pack_bf16(v[1].x, v[1].y); q0.w = pack_bf16(v[1].z, v[1].w);
  q1.x = pack_bf16(v[2].x, v[2].y); q1.y = pack_bf16(v[2].z, v[2].w);
  q1.z = pack_bf16(v[3].x, v[3].y); q1.w = pack_bf16(v[3].z, v[3].w);
  *(uint4*)d = q0;
  *((uint4*)d + 1) = q1;
}

// ---------------------------------------------------------------------------
// Prep: w1 -> g_w1b (vec cvt), pat -> g_pat (vec cvt),
//       wT -> g_wTt via smem-tiled 64x64 transpose (coalesced both sides).
// grid: 64 (w1) + 512 (pat) + 32 (wT tiles) = 608 blocks.
// ---------------------------------------------------------------------------
__global__ __launch_bounds__(256) void kprep_all(const float* __restrict__ w1,
                                                 const float* __restrict__ wT,
                                                 const float* __restrict__ pat) {
  __shared__ __align__(16) float sm[64 * 68];
  const int bid = blockIdx.x;
  const int t = threadIdx.x;
  if (bid < 64) {  // w1: 65536 floats, vec4
    const int idx = (bid * 256 + t) * 4;
    const float4 v = *(const float4*)(w1 + idx);
    uint2 o;
    o.x = pack_bf16(v.x, v.y);
    o.y = pack_bf16(v.z, v.w);
    *(uint2*)&g_w1b[idx] = o;
  } else if (bid < 576) {  // patterns: 524288 floats, vec4
    const int idx = ((bid - 576 + 512) * 256 + t) * 4 - 512 * 1024 * 4;
    const int i2 = ((bid - 64) * 256 + t) * 4;
    (void)idx;
    const float4 v = *(const float4*)(pat + i2);
    uint2 o;
    o.x = pack_bf16(v.x, v.y);
    o.y = pack_bf16(v.z, v.w);
    *(uint2*)&g_pat[i2] = o;
  } else {  // wT transpose: 32 tiles of 64x64
    const int tb = bid - 576;
    const int g = tb >> 4, ti = (tb >> 2) & 3, tc = tb & 3;
    // load tile: rows i = ti*64.., cols co2 = tc*64..  (coalesced float4)
    const float* src = wT + ((size_t)(g * 256 + ti * 64)) * 256 + tc * 64;
#pragma unroll
    for (int k = 0; k < 4; ++k) {
      const int idx = t + k * 256;
      const int r = idx >> 4, c4 = (idx & 15) * 4;
      *(float4*)&sm[r * 68 + c4] = *(const float4*)(src + (size_t)r * 256 + c4);
    }
    __syncthreads();
    // store transposed: out[g][co2][i] bf16, rows co2, cols i (vec uint2)
    __nv_bfloat16* dst = g_wTt + (size_t)g * 65536 + (size_t)(tc * 64) * 256 + ti * 64;
#pragma unroll
    for (int k = 0; k < 4; ++k) {
      const int idx = t + k * 256;
      const int orow = idx >> 4, ocol = (idx & 15) * 4;
      uint2 o;
      o.x = pack_bf16(sm[(ocol + 0) * 68 + orow], sm[(ocol + 1) * 68 + orow]);
      o.y = pack_bf16(sm[(ocol + 2) * 68 + orow], sm[(ocol + 3) * 68 + orow]);
      *(uint2*)&dst[(size_t)orow * 256 + ocol] = o;
    }
  }
}

// ---------------------------------------------------------------------------
// k1: HMMA grouped 1x1 conv + bias + ReLU + maxpool2 -> g_hp bf16 (r7 version)
// ---------------------------------------------------------------------------
__global__ __launch_bounds__(256) void k1_hmma(const float* __restrict__ x,
                                               const float* __restrict__ b1) {
  __shared__ __align__(16) char smem[37888];  // A 2x10240 | B 2x8704
  const int t = threadIdx.x, w = t >> 5, lid = t & 31;
  const int wm = w >> 2, wn = w & 3;
  const int bx = blockIdx.x, by = blockIdx.y, bz = blockIdx.z;
  const int b = bz >> 1, g = bz & 1;
  const uint32_t sAb = (uint32_t)__cvta_generic_to_shared(smem);
  const char* Ag = (const char*)(g_w1b + (size_t)(g * 256 + by * 128) * 128);
  const float* xB = x + ((size_t)(b * 256 + g * 128)) * 2048 + bx * 128;

  const int brow = t >> 3, bcq = t & 7;
  const float* xrow = xB + (size_t)brow * 2048 + bcq * 16;

  auto ldA = [&](int s, int it) {
#pragma unroll
    for (int i = 0; i < 2; ++i) {
      const int idx = t + i * 256;
      const int row = idx >> 2, ch = idx & 3;
      cp_async16(sAb + s * 10240 + row * 80 + ch * 16,
                 Ag + row * 256 + it * 64 + ch * 16);
    }
    CP_COMMIT();
  };

  float4 v[4];
  auto ldB = [&](int it) {
    const float4* p = (const float4*)(xrow + (size_t)it * 32 * 2048);
#pragma unroll
    for (int q = 0; q < 4; ++q) v[q] = p[q];
  };
  auto stB = [&](int s) {
    cvt_store16(smem + 20480 + s * 8704 + brow * 272 + bcq * 32, v);
  };

  float acc[4][4][4];
#pragma unroll
  for (int mt = 0; mt < 4; ++mt)
#pragma unroll
    for (int nt = 0; nt < 4; ++nt)
#pragma unroll
      for (int i = 0; i < 4; ++i) acc[mt][nt][i] = 0.f;

  ldA(0, 0);
  ldB(0);
  const uint32_t aAddr0 = sAb + (wm * 64 + (lid & 15)) * 80 + (lid >> 4) * 16;
  const uint32_t bAddr0 = sAb + 20480 +
      (((lid >> 3) & 1) * 8 + (lid & 7)) * 272 + (wn * 32 + (lid >> 4) * 8) * 2;

#pragma unroll 1
  for (int it = 0; it < 4; ++it) {
    if (it + 1 < 4) {
      ldA((it + 1) & 1, it + 1);
      CP_WAIT(1);
    } else {
      CP_WAIT(0);
    }
    stB(it & 1);
    __syncthreads();
    if (it + 1 < 4) ldB(it + 1);
    const uint32_t sOA = (uint32_t)(it & 1) * 10240;
    const uint32_t sOB = (uint32_t)(it & 1) * 8704;
#pragma unroll
    for (int ks = 0; ks < 2; ++ks) {
      uint32_t afr[4][4];
      uint32_t bfr[4][2];
#pragma unroll
      for (int mt = 0; mt < 4; ++mt)
        ldsm_x4(afr[mt], aAddr0 + sOA + mt * 16 * 80 + ks * 32);
#pragma unroll
      for (int nt2 = 0; nt2 < 2; ++nt2) {
        uint32_t r4[4];
        ldsm_x4_t(r4, bAddr0 + sOB + ks * 16 * 272 + nt2 * 32);
        bfr[nt2 * 2 + 0][0] = r4[0]; bfr[nt2 * 2 + 0][1] = r4[1];
        bfr[nt2 * 2 + 1][0] = r4[2]; bfr[nt2 * 2 + 1][1] = r4[3];
      }
#pragma unroll
      for (int mt = 0; mt < 4; ++mt)
#pragma unroll
        for (int nt = 0; nt < 4; ++nt)
          mma_16816(acc[mt][nt], afr[mt], bfr[nt][0], bfr[nt][1]);
    }
    __syncthreads();
  }

  __nv_bfloat16* sH = (__nv_bfloat16*)smem;  // [128][72]
#pragma unroll
  for (int mt = 0; mt < 4; ++mt) {
    const int m = wm * 64 + mt * 16 + (lid >> 2);
    const int og = g * 256 + by * 128 + m;
    const float bias0 = b1[og];
    const float bias1 = b1[og + 8];
#pragma unroll
    for (int nt = 0; nt < 4; ++nt) {
      const int np = wn * 16 + nt * 4 + (lid & 3);
      sH[m * 72 + np] =
          __float2bfloat16(fmaxf(fmaxf(acc[mt][nt][0], acc[mt][nt][1]) + bias0, 0.f));
      sH[(m + 8) * 72 + np] =
          __float2bfloat16(fmaxf(fmaxf(acc[mt][nt][2], acc[mt][nt][3]) + bias1, 0.f));
    }
  }
  __syncthreads();
  const size_t rowbase = (size_t)(b * 512 + g * 256 + by * 128);
  const int colbase = bx * 64;
#pragma unroll
  for (int p = 0; p < 4; ++p) {
    const int idx = t + p * 256;
    const int row = idx >> 3, ch = idx & 7;
    *(uint4*)&g_hp[(rowbase + row) * 1024 + colbase + ch * 8] =
        *(uint4*)&sH[row * 72 + ch * 8];
  }
}

// ---------------------------------------------------------------------------
// k2: HMMA scores = Hp @ P^T (K=1024) -> g_scb bf16
// 3-stage cp.async both operands, ONE sync per iter. dyn smem 61440.
// __launch_bounds__(256,2) -> 2 CTAs/SM.
// ---------------------------------------------------------------------------
__global__ __launch_bounds__(256, 2) void kgemm_scores() {
  constexpr int ITERS = 32;
  extern __shared__ __align__(16) char smem[];  // A 3x10240 | B 3x10240
  const int t = threadIdx.x, w = t >> 5, lid = t & 31;
  const int wm = w >> 2, wn = w & 3;
  const int n0 = blockIdx.x * 128;
  const int r0 = blockIdx.y * 128;
  const uint32_t sAb = (uint32_t)__cvta_generic_to_shared(smem);
  constexpr uint32_t BOFF = 30720;
  const char* Ab = (const char*)(g_hp + (size_t)r0 * 1024);
  const char* Bb = (const char*)(g_pat + (size_t)n0 * 1024);

  const int row2[2] = {(t + 0) >> 2, (t + 256) >> 2};
  const int ch2[2]  = {(t + 0) & 3, (t + 256) & 3};
  auto load_tile = [&](int s, int it) {
#pragma unroll
    for (int i = 0; i < 2; ++i) {
      const size_t go = (size_t)row2[i] * 2048 + it * 64 + ch2[i] * 16;
      const uint32_t so = row2[i] * 80 + ch2[i] * 16;
      cp_async16(sAb + s * 10240 + so, Ab + go);
      cp_async16(sAb + BOFF + s * 10240 + so, Bb + go);
    }
    CP_COMMIT();
  };

  float acc[4][4][4];
#pragma unroll
  for (int mt = 0; mt < 4; ++mt)
#pragma unroll
    for (int nt = 0; nt < 4; ++nt)
#pragma unroll
      for (int i = 0; i < 4; ++i) acc[mt][nt][i] = 0.f;

  load_tile(0, 0);
  load_tile(1, 1);
  const uint32_t aAddr0 = sAb + (wm * 64 + (lid & 15)) * 80 + (lid >> 4) * 16;
  const uint32_t bAddr0 = sAb + BOFF +
      (wn * 32 + ((lid >> 4) ? 8 : 0) + (lid & 7)) * 80 + ((lid >> 3) & 1) * 16;

  int s3 = 0;
#pragma unroll 1
  for (int it = 0; it < ITERS; ++it) {
    if (it + 1 < ITERS) { CP_WAIT(1); } else { CP_WAIT(0); }
    __syncthreads();
    int nx = s3 + 2; if (nx >= 3) nx -= 3;
    if (it + 2 < ITERS) load_tile(nx, it + 2);
    const uint32_t sO = (uint32_t)s3 * 10240;
#pragma unroll
    for (int ks = 0; ks < 2; ++ks) {
      uint32_t afr[4][4];
      uint32_t bfr[4][2];
#pragma unroll
      for (int mt = 0; mt < 4; ++mt)
        ldsm_x4(afr[mt], aAddr0 + sO + mt * 16 * 80 + ks * 32);
#pragma unroll
      for (int nt2 = 0; nt2 < 2; ++nt2) {
        uint32_t r4[4];
        ldsm_x4(r4, bAddr0 + sO + nt2 * 16 * 80 + ks * 32);
        bfr[nt2 * 2 + 0][0] = r4[0]; bfr[nt2 * 2 + 0][1] = r4[1];
        bfr[nt2 * 2 + 1][0] = r4[2]; bfr[nt2 * 2 + 1][1] = r4[3];
      }
#pragma unroll
      for (int mt = 0; mt < 4; ++mt)
#pragma unroll
        for (int nt = 0; nt < 4; ++nt)
          mma_16816(acc[mt][nt], afr[mt], bfr[nt][0], bfr[nt][1]);
    }
    s3 = (s3 + 1 == 3) ? 0 : s3 + 1;
  }

  __nv_bfloat16* Crow = g_scb + (size_t)(r0 + wm * 64) * 512 + n0 + wn * 32;
  const int rr = lid >> 2;
  const int cc = (lid & 3) * 2;
#pragma unroll
  for (int mt = 0; mt < 4; ++mt)
#pragma unroll
    for (int nt = 0; nt < 4; ++nt) {
      *(uint32_t*)&Crow[(size_t)(mt * 16 + rr) * 512 + nt * 8 + cc] =
          pack_bf16(acc[mt][nt][0], acc[mt][nt][1]);
      *(uint32_t*)&Crow[(size_t)(mt * 16 + rr + 8) * 512 + nt * 8 + cc] =
          pack_bf16(acc[mt][nt][2], acc[mt][nt][3]);
    }
}

// ---------------------------------------------------------------------------
// k3: softmax over m=512 — warp per row, bf16 in/out
// ---------------------------------------------------------------------------
__global__ __launch_bounds__(256) void k3_softmax() {
  const int wid = threadIdx.x >> 5, lane = threadIdx.x & 31;
  const size_t row = (size_t)blockIdx.x * 8 + wid;
  const uint4* rp = (const uint4*)(g_scb + row * 512);
  const uint4 q0 = rp[lane];
  const uint4 q1 = rp[lane + 32];

  float f[16];
  {
    const uint32_t us[8] = {q0.x, q0.y, q0.z, q0.w, q1.x, q1.y, q1.z, q1.w};
#pragma unroll
    for (int i = 0; i < 8; ++i) {
      const __nv_bfloat162 p = *(const __nv_bfloat162*)&us[i];
      f[2 * i] = __bfloat162float(p.x);
      f[2 * i + 1] = __bfloat162float(p.y);
    }
  }
  float m = f[0];
#pragma unroll
  for (int i = 1; i < 16; ++i) m = fmaxf(m, f[i]);
#pragma unroll
  for (int o = 16; o; o >>= 1) m = fmaxf(m, __shfl_xor_sync(0xffffffffu, m, o));
  float s = 0.f;
#pragma unroll
  for (int i = 0; i < 16; ++i) {
    f[i] = __expf(f[i] - m);
    s += f[i];
  }
#pragma unroll
  for (int o = 16; o; o >>= 1) s += __shfl_xor_sync(0xffffffffu, s, o);
  const float inv = 1.f / s;

  uint4 o0, o1;
  o0.x = pack_bf16(f[0] * inv, f[1] * inv);
  o0.y = pack_bf16(f[2] * inv, f[3] * inv);
  o0.z = pack_bf16(f[4] * inv, f[5] * inv);
  o0.w = pack_bf16(f[6] * inv, f[7] * inv);
  o1.x = pack_bf16(f[8] * inv, f[9] * inv);
  o1.y = pack_bf16(f[10] * inv, f[11] * inv);
  o1.z = pack_bf16(f[12] * inv, f[13] * inv);
  o1.w = pack_bf16(f[14] * inv, f[15] * inv);
  uint4* op = (uint4*)(g_at + row * 512);
  op[lane] = o0;
  op[lane + 32] = o1;
}

// ---------------------------------------------------------------------------
// k4: HMMA retrieval = Attn @ P (K=512) -> g_hrT bf16 transposed
// 3-stage cp.async both operands (B trans from g_pat), ONE sync/iter.
// dyn smem 56832. __launch_bounds__(256,2).
// ---------------------------------------------------------------------------
__global__ __launch_bounds__(256, 2) void kgemm_retrieve() {
  constexpr int ITERS = 16;
  extern __shared__ __align__(16) char smem[];  // A 3x10240 | B 3x8704
  const int t = threadIdx.x, w = t >> 5, lid = t & 31;
  const int wm = w >> 2, wn = w & 3;
  const int n0 = blockIdx.x * 128;  // lp
  const int r0 = blockIdx.y * 128;  // attn row
  const uint32_t sAb = (uint32_t)__cvta_generic_to_shared(smem);
  constexpr uint32_t BOFF = 30720;
  const char* Ab = (const char*)(g_at + (size_t)r0 * 512);
  const char* Bb = (const char*)(g_pat + n0);

  const int arow[2] = {(t + 0) >> 2, (t + 256) >> 2};
  const int ach[2]  = {(t + 0) & 3, (t + 256) & 3};
  const int brow[2] = {(t + 0) >> 4, (t + 256) >> 4};
  const int bch[2]  = {(t + 0) & 15, (t + 256) & 15};
  auto load_tile = [&](int s, int it) {
#pragma unroll
    for (int i = 0; i < 2; ++i) {
      cp_async16(sAb + s * 10240 + arow[i] * 80 + ach[i] * 16,
                 Ab + (size_t)arow[i] * 1024 + it * 64 + ach[i] * 16);
      cp_async16(sAb + BOFF + s * 8704 + brow[i] * 272 + bch[i] * 16,
                 Bb + (size_t)(it * 32 + brow[i]) * 2048 + bch[i] * 16);
    }
    CP_COMMIT();
  };

  float acc[4][4][4];
#pragma unroll
  for (int mt = 0; mt < 4; ++mt)
#pragma unroll
    for (int nt = 0; nt < 4; ++nt)
#pragma unroll
      for (int i = 0; i < 4; ++i) acc[mt][nt][i] = 0.f;

  load_tile(0, 0);
  load_tile(1, 1);
  const uint32_t aAddr0 = sAb + (wm * 64 + (lid & 15)) * 80 + (lid >> 4) * 16;
  const uint32_t bAddr0 = sAb + BOFF +
      (((lid >> 3) & 1) * 8 + (lid & 7)) * 272 + (wn * 32 + (lid >> 4) * 8) * 2;

  int s3 = 0;
#pragma unroll 1
  for (int it = 0; it < ITERS; ++it) {
    if (it + 1 < ITERS) { CP_WAIT(1); } else { CP_WAIT(0); }
    __syncthreads();
    int nx = s3 + 2; if (nx >= 3) nx -= 3;
    if (it + 2 < ITERS) load_tile(nx, it + 2);
    const uint32_t sOA = (uint32_t)s3 * 10240;
    const uint32_t sOB = (uint32_t)s3 * 8704;
#pragma unroll
    for (int ks = 0; ks < 2; ++ks) {
      uint32_t afr[4][4];
      uint32_t bfr[4][2];
#pragma unroll
      for (int mt = 0; mt < 4; ++mt)
        ldsm_x4(afr[mt], aAddr0 + sOA + mt * 16 * 80 + ks * 32);
#pragma unroll
      for (int nt2 = 0; nt2 < 2; ++nt2) {
        uint32_t r4[4];
        ldsm_x4_t(r4, bAddr0 + sOB + ks * 16 * 272 + nt2 * 32);
        bfr[nt2 * 2 + 0][0] = r4[0]; bfr[nt2 * 2 + 0][1] = r4[1];
        bfr[nt2 * 2 + 1][0] = r4[2]; bfr[nt2 * 2 + 1][1] = r4[3];
      }
#pragma unroll
      for (int mt = 0; mt < 4; ++mt)
#pragma unroll
        for (int nt = 0; nt < 4; ++nt)
          mma_16816(acc[mt][nt], afr[mt], bfr[nt][0], bfr[nt][1]);
    }
    s3 = (s3 + 1 == 3) ? 0 : s3 + 1;
  }
  __syncthreads();

  // transposed bf16 epilogue: stage [l][c], then coalesced rows of g_hrT
  __nv_bfloat16* sT = (__nv_bfloat16*)smem;  // [128 l][136 c]
#pragma unroll
  for (int mt = 0; mt < 4; ++mt) {
    const int m = wm * 64 + mt * 16 + (lid >> 2);
#pragma unroll
    for (int nt = 0; nt < 4; ++nt) {
      const int n = wn * 32 + nt * 8 + (lid & 3) * 2;
      sT[n * 136 + m] = __float2bfloat16(acc[mt][nt][0]);
      sT[(n + 1) * 136 + m] = __float2bfloat16(acc[mt][nt][1]);
      sT[n * 136 + m + 8] = __float2bfloat16(acc[mt][nt][2]);
      sT[(n + 1) * 136 + m + 8] = __float2bfloat16(acc[mt][nt][3]);
    }
  }
  __syncthreads();
  const int b = r0 >> 9;
  const int c0b = r0 & 511;
#pragma unroll
  for (int p = 0; p < 8; ++p) {
    const int idx = t + p * 256;
    const int row = idx >> 4, ch = idx & 15;
    *(uint4*)&g_hrT[((size_t)b * 1024 + n0 + row) * 512 + c0b + ch * 8] =
        *(uint4*)&sT[row * 136 + ch * 8];
  }
}

// ---------------------------------------------------------------------------
// k5: HMMA grouped ConvT(k=2,s=2) + bias + ReLU + residual
// 3-stage cp.async both operands, ONE sync/iter. dyn smem 61440.
// __launch_bounds__(256,2).
// ---------------------------------------------------------------------------
__global__ __launch_bounds__(256, 2) void k5_hmma(
    const float* __restrict__ x, const float* __restrict__ bT,
    const float* __restrict__ rzp, float* __restrict__ out) {
  constexpr int ITERS = 8;
  extern __shared__ __align__(16) char smem[];  // A 3x10240 | B 3x10240
  const int t = threadIdx.x, w = t >> 5, lid = t & 31;
  const int wm = w >> 2, wn = w & 3;
  const int bx = blockIdx.x, by = blockIdx.y, bz = blockIdx.z;
  const int b = bz >> 1, g = bz & 1;
  const uint32_t sAb = (uint32_t)__cvta_generic_to_shared(smem);
  constexpr uint32_t BOFF = 30720;
  const char* Ab =
      (const char*)(g_hrT + ((size_t)b * 1024 + by * 128) * 512 + g * 256);
  const char* Bb = (const char*)(g_wTt + (size_t)g * 65536 + (size_t)bx * 128 * 256);

  const int row2[2] = {(t + 0) >> 2, (t + 256) >> 2};
  const int ch2[2]  = {(t + 0) & 3, (t + 256) & 3};
  auto load_tile = [&](int s, int it) {
#pragma unroll
    for (int i = 0; i < 2; ++i) {
      const uint32_t so = row2[i] * 80 + ch2[i] * 16;
      cp_async16(sAb + s * 10240 + so,
                 Ab + (size_t)row2[i] * 1024 + it * 64 + ch2[i] * 16);
      cp_async16(sAb + BOFF + s * 10240 + so,
                 Bb + (size_t)row2[i] * 512 + it * 64 + ch2[i] * 16);
    }
    CP_COMMIT();
  };

  float acc[4][4][4];
#pragma unroll
  for (int mt = 0; mt < 4; ++mt)
#pragma unroll
    for (int nt = 0; nt < 4; ++nt)
#pragma unroll
      for (int i = 0; i < 4; ++i) acc[mt][nt][i] = 0.f;

  load_tile(0, 0);
  load_tile(1, 1);
  const uint32_t aAddr0 = sAb + (wm * 64 + (lid & 15)) * 80 + (lid >> 4) * 16;
  const uint32_t bAddr0 = sAb + BOFF +
      (wn * 32 + ((lid >> 4) ? 8 : 0) + (lid & 7)) * 80 + ((lid >> 3) & 1) * 16;

  int s3 = 0;
#pragma unroll 1
  for (int it = 0; it < ITERS; ++it) {
    if (it + 1 < ITERS) { CP_WAIT(1); } else { CP_WAIT(0); }
    __syncthreads();
    int nx = s3 + 2; if (nx >= 3) nx -= 3;
    if (it + 2 < ITERS) load_tile(nx, it + 2);
    const uint32_t sO = (uint32_t)s3 * 10240;
#pragma unroll
    for (int ks = 0; ks < 2; ++ks) {
      uint32_t afr[4][4];
      uint32_t bfr[4][2];
#pragma unroll
      for (int mt = 0; mt < 4; ++mt)
        ldsm_x4(afr[mt], aAddr0 + sO + mt * 16 * 80 + ks * 32);
#pragma unroll
      for (int nt2 = 0; nt2 < 2; ++nt2) {
        uint32_t r4[4];
        ldsm_x4(r4, bAddr0 + sO + nt2 * 16 * 80 + ks * 32);
        bfr[nt2 * 2 + 0][0] = r4[0]; bfr[nt2 * 2 + 0][1] = r4[1];
        bfr[nt2 * 2 + 1][0] = r4[2]; bfr[nt2 * 2 + 1][1] = r4[3];
      }
#pragma unroll
      for (int mt = 0; mt < 4; ++mt)
#pragma unroll
        for (int nt = 0; nt < 4; ++nt)
          mma_16816(acc[mt][nt], afr[mt], bfr[nt][0], bfr[nt][1]);
    }
    s3 = (s3 + 1 == 3) ? 0 : s3 + 1;
  }
  __syncthreads();

  // epilogue: bias + relu -> bf16 stage y[co 64][l 268]; then residual write
  __nv_bfloat16* sY = (__nv_bfloat16*)smem;
  float biasv[4];
#pragma unroll
  for (int nt = 0; nt < 4; ++nt) {
    const int co_l = wn * 16 + nt * 4 + (lid & 3);
    biasv[nt] = bT[g * 128 + bx * 64 + co_l];
  }
#pragma unroll
  for (int mt = 0; mt < 4; ++mt) {
    const int m = wm * 64 + mt * 16 + (lid >> 2);
#pragma unroll
    for (int nt = 0; nt < 4; ++nt) {
      const int co_l = wn * 16 + nt * 4 + (lid & 3);
      __nv_bfloat162 p0 = __floats2bfloat162_rn(
          fmaxf(acc[mt][nt][0] + biasv[nt], 0.f),
          fmaxf(acc[mt][nt][1] + biasv[nt], 0.f));
      __nv_bfloat162 p1 = __floats2bfloat162_rn(
          fmaxf(acc[mt][nt][2] + biasv[nt], 0.f),
          fmaxf(acc[mt][nt][3] + biasv[nt], 0.f));
      *(__nv_bfloat162*)&sY[co_l * 268 + 2 * m] = p0;
      *(__nv_bfloat162*)&sY[co_l * 268 + 2 * (m + 8)] = p1;
    }
  }
  __syncthreads();
  const float rz = rzp[0];
  const int co_r = t >> 2;
  const int colb = (t & 3) * 4;
  const int cog = g * 128 + bx * 64 + co_r;
  const size_t rowoff = ((size_t)b * 256 + cog) * 2048 + by * 256;
#pragma unroll
  for (int j = 0; j < 16; ++j) {
    const int col = colb + j * 16;
    const uint32_t* yp = (const uint32_t*)&sY[co_r * 268 + col];
    __nv_bfloat162 y0 = *(const __nv_bfloat162*)&yp[0];
    __nv_bfloat162 y1 = *(const __nv_bfloat162*)&yp[1];
    const float4 xv = *(const float4*)(x + rowoff + col);
    float4 o4;
    o4.x = xv.x + rz * __bfloat162float(y0.x);
    o4.y = xv.y + rz * __bfloat162float(y0.y);
    o4.z = xv.z + rz * __bfloat162float(y1.x);
    o4.w = xv.w + rz * __bfloat162float(y1.y);
    *(float4*)(out + rowoff + col) = o4;
  }
}

// ---------------------------------------------------------------------------
extern "C" void kernel_launch(void* const* d_in, const int* in_sizes, int n_in,
                              void* d_out, int out_size) {
  (void)in_sizes; (void)n_in; (void)out_size;
  const float* x        = (const float*)d_in[0];
  const float* w1       = (const float*)d_in[1];
  const float* b1       = (const float*)d_in[2];
  const float* patterns = (const float*)d_in[3];
  const float* wT       = (const float*)d_in[4];
  const float* bT       = (const float*)d_in[5];
  const float* RZ       = (const float*)d_in[6];
  float* out            = (float*)d_out;

  cudaFuncSetAttribute(kgemm_scores,
                       cudaFuncAttributeMaxDynamicSharedMemorySize, 61440);
  cudaFuncSetAttribute(kgemm_retrieve,
                       cudaFuncAttributeMaxDynamicSharedMemorySize, 56832);
  cudaFuncSetAttribute(k5_hmma,
                       cudaFuncAttributeMaxDynamicSharedMemorySize, 61440);

  kprep_all<<<608, 256>>>(w1, wT, patterns);
  k1_hmma<<<dim3(16, 2, 32), 256>>>(x, b1);
  kgemm_scores<<<dim3(4, 64), 256, 61440>>>();
  k3_softmax<<<kRows / 8, 256>>>();
  kgemm_retrieve<<<dim3(8, 64), 256, 56832>>>();
  k5_hmma<<<dim3(2, 8, 32), 256, 61440>>>(x, bT, RZ, out);
}

// round 10
// speedup vs baseline: 1.2044x; 1.0638x over previous
#include <cuda_runtime.h>
#include <cuda_bf16.h>
#include <cstdint>

namespace {
constexpr int kB   = 16;
constexpr int kRows = kB * 512;  // 8192
}

// ---------------- scratch (device globals; no allocation) -------------------
__device__ __align__(16) __nv_bfloat16 g_w1b[512 * 128];       // w1 bf16
__device__ __align__(16) __nv_bfloat16 g_wTt[2 * 256 * 256];   // wT^T bf16 [g][co2][i]
__device__ __align__(16) __nv_bfloat16 g_hp[kRows * 1024];     // pooled hidden bf16
__device__ __align__(16) __nv_bfloat16 g_scb[kRows * 512];     // scores bf16
__device__ __align__(16) __nv_bfloat16 g_at[kRows * 512];      // attn bf16
__device__ __align__(16) __nv_bfloat16 g_hrT[kB * 1024 * 512]; // retrieved^T bf16
__device__ __align__(16) __nv_bfloat16 g_pat[512 * 1024];      // patterns bf16 [m][lp]

// ---------------- PTX helpers ------------------------------------------------
__device__ __forceinline__ void cp_async16(uint32_t dst, const void* src) {
  asm volatile("cp.async.cg.shared.global [%0], [%1], 16;\n" ::"r"(dst), "l"(src));
}
#define CP_COMMIT() asm volatile("cp.async.commit_group;\n" ::: "memory")
#define CP_WAIT(n) asm volatile("cp.async.wait_group %0;\n" ::"n"(n) : "memory")

__device__ __forceinline__ void ldsm_x4(uint32_t (&r)[4], uint32_t addr) {
  asm volatile(
      "ldmatrix.sync.aligned.m8n8.x4.shared.b16 {%0,%1,%2,%3}, [%4];"
      : "=r"(r[0]), "=r"(r[1]), "=r"(r[2]), "=r"(r[3])
      : "r"(addr));
}
__device__ __forceinline__ void ldsm_x4_t(uint32_t (&r)[4], uint32_t addr) {
  asm volatile(
      "ldmatrix.sync.aligned.m8n8.x4.trans.shared.b16 {%0,%1,%2,%3}, [%4];"
      : "=r"(r[0]), "=r"(r[1]), "=r"(r[2]), "=r"(r[3])
      : "r"(addr));
}

__device__ __forceinline__ void mma_16816(float (&c)[4], const uint32_t (&a)[4],
                                          const uint32_t b0, const uint32_t b1) {
  asm volatile(
      "mma.sync.aligned.m16n8k16.row.col.f32.bf16.bf16.f32 "
      "{%0,%1,%2,%3}, {%4,%5,%6,%7}, {%8,%9}, {%0,%1,%2,%3};"
      : "+f"(c[0]), "+f"(c[1]), "+f"(c[2]), "+f"(c[3])
      : "r"(a[0]), "r"(a[1]), "r"(a[2]), "r"(a[3]), "r"(b0), "r"(b1));
}

__device__ __forceinline__ uint32_t pack_bf16(float a, float b) {
  __nv_bfloat162 p = __floats2bfloat162_rn(a, b);
  return *(uint32_t*)&p;
}

__device__ __forceinline__ void cvt_store16(char* d, const float4 (&v)[4]) {
  uint4 q0, q1;
  q0.x = pack_bf16(v[0].x, v[0].y); q0.y = pack_bf16(v[0].z, v[0].w);
  q0.z = pack_bf16(v[1].x, v[1].y); q0.w = pack_bf16(v[1].z, v[1].w);
  q1.x = pack_bf16(v[2].x, v[2].y); q1.y = pack_bf16(v[2].z, v[2].w);
  q1.z = pack_bf16(v[3].x, v[3].y); q1.w = pack_bf16(v[3].z, v[3].w);
  *(uint4*)d = q0;
  *((uint4*)d + 1) = q1;
}

// ---------------------------------------------------------------------------
// Prep: w1 -> g_w1b, pat -> g_pat (vec cvt); wT -> g_wTt via tiled transpose.
// ---------------------------------------------------------------------------
__global__ __launch_bounds__(256) void kprep_all(const float* __restrict__ w1,
                                                 const float* __restrict__ wT,
                                                 const float* __restrict__ pat) {
  __shared__ __align__(16) float sm[64 * 68];
  const int bid = blockIdx.x;
  const int t = threadIdx.x;
  if (bid < 64) {
    const int idx = (bid * 256 + t) * 4;
    const float4 v = *(const float4*)(w1 + idx);
    uint2 o;
    o.x = pack_bf16(v.x, v.y);
    o.y = pack_bf16(v.z, v.w);
    *(uint2*)&g_w1b[idx] = o;
  } else if (bid < 576) {
    const int i2 = ((bid - 64) * 256 + t) * 4;
    const float4 v = *(const float4*)(pat + i2);
    uint2 o;
    o.x = pack_bf16(v.x, v.y);
    o.y = pack_bf16(v.z, v.w);
    *(uint2*)&g_pat[i2] = o;
  } else {
    const int tb = bid - 576;
    const int g = tb >> 4, ti = (tb >> 2) & 3, tc = tb & 3;
    const float* src = wT + ((size_t)(g * 256 + ti * 64)) * 256 + tc * 64;
#pragma unroll
    for (int k = 0; k < 4; ++k) {
      const int idx = t + k * 256;
      const int r = idx >> 4, c4 = (idx & 15) * 4;
      *(float4*)&sm[r * 68 + c4] = *(const float4*)(src + (size_t)r * 256 + c4);
    }
    __syncthreads();
    __nv_bfloat16* dst = g_wTt + (size_t)g * 65536 + (size_t)(tc * 64) * 256 + ti * 64;
#pragma unroll
    for (int k = 0; k < 4; ++k) {
      const int idx = t + k * 256;
      const int orow = idx >> 4, ocol = (idx & 15) * 4;
      uint2 o;
      o.x = pack_bf16(sm[(ocol + 0) * 68 + orow], sm[(ocol + 1) * 68 + orow]);
      o.y = pack_bf16(sm[(ocol + 2) * 68 + orow], sm[(ocol + 3) * 68 + orow]);
      *(uint2*)&dst[(size_t)orow * 256 + ocol] = o;
    }
  }
}

// ---------------------------------------------------------------------------
// k1: HMMA grouped 1x1 conv + bias + ReLU + maxpool2 -> g_hp bf16 (r7 version)
// ---------------------------------------------------------------------------
__global__ __launch_bounds__(256) void k1_hmma(const float* __restrict__ x,
                                               const float* __restrict__ b1) {
  __shared__ __align__(16) char smem[37888];
  const int t = threadIdx.x, w = t >> 5, lid = t & 31;
  const int wm = w >> 2, wn = w & 3;
  const int bx = blockIdx.x, by = blockIdx.y, bz = blockIdx.z;
  const int b = bz >> 1, g = bz & 1;
  const uint32_t sAb = (uint32_t)__cvta_generic_to_shared(smem);
  const char* Ag = (const char*)(g_w1b + (size_t)(g * 256 + by * 128) * 128);
  const float* xB = x + ((size_t)(b * 256 + g * 128)) * 2048 + bx * 128;

  const int brow = t >> 3, bcq = t & 7;
  const float* xrow = xB + (size_t)brow * 2048 + bcq * 16;

  auto ldA = [&](int s, int it) {
#pragma unroll
    for (int i = 0; i < 2; ++i) {
      const int idx = t + i * 256;
      const int row = idx >> 2, ch = idx & 3;
      cp_async16(sAb + s * 10240 + row * 80 + ch * 16,
                 Ag + row * 256 + it * 64 + ch * 16);
    }
    CP_COMMIT();
  };

  float4 v[4];
  auto ldB = [&](int it) {
    const float4* p = (const float4*)(xrow + (size_t)it * 32 * 2048);
#pragma unroll
    for (int q = 0; q < 4; ++q) v[q] = p[q];
  };
  auto stB = [&](int s) {
    cvt_store16(smem + 20480 + s * 8704 + brow * 272 + bcq * 32, v);
  };

  float acc[4][4][4];
#pragma unroll
  for (int mt = 0; mt < 4; ++mt)
#pragma unroll
    for (int nt = 0; nt < 4; ++nt)
#pragma unroll
      for (int i = 0; i < 4; ++i) acc[mt][nt][i] = 0.f;

  ldA(0, 0);
  ldB(0);
  const uint32_t aAddr0 = sAb + (wm * 64 + (lid & 15)) * 80 + (lid >> 4) * 16;
  const uint32_t bAddr0 = sAb + 20480 +
      (((lid >> 3) & 1) * 8 + (lid & 7)) * 272 + (wn * 32 + (lid >> 4) * 8) * 2;

#pragma unroll 1
  for (int it = 0; it < 4; ++it) {
    if (it + 1 < 4) {
      ldA((it + 1) & 1, it + 1);
      CP_WAIT(1);
    } else {
      CP_WAIT(0);
    }
    stB(it & 1);
    __syncthreads();
    if (it + 1 < 4) ldB(it + 1);
    const uint32_t sOA = (uint32_t)(it & 1) * 10240;
    const uint32_t sOB = (uint32_t)(it & 1) * 8704;
#pragma unroll
    for (int ks = 0; ks < 2; ++ks) {
      uint32_t afr[4][4];
      uint32_t bfr[4][2];
#pragma unroll
      for (int mt = 0; mt < 4; ++mt)
        ldsm_x4(afr[mt], aAddr0 + sOA + mt * 16 * 80 + ks * 32);
#pragma unroll
      for (int nt2 = 0; nt2 < 2; ++nt2) {
        uint32_t r4[4];
        ldsm_x4_t(r4, bAddr0 + sOB + ks * 16 * 272 + nt2 * 32);
        bfr[nt2 * 2 + 0][0] = r4[0]; bfr[nt2 * 2 + 0][1] = r4[1];
        bfr[nt2 * 2 + 1][0] = r4[2]; bfr[nt2 * 2 + 1][1] = r4[3];
      }
#pragma unroll
      for (int mt = 0; mt < 4; ++mt)
#pragma unroll
        for (int nt = 0; nt < 4; ++nt)
          mma_16816(acc[mt][nt], afr[mt], bfr[nt][0], bfr[nt][1]);
    }
    __syncthreads();
  }

  __nv_bfloat16* sH = (__nv_bfloat16*)smem;  // [128][72]
#pragma unroll
  for (int mt = 0; mt < 4; ++mt) {
    const int m = wm * 64 + mt * 16 + (lid >> 2);
    const int og = g * 256 + by * 128 + m;
    const float bias0 = b1[og];
    const float bias1 = b1[og + 8];
#pragma unroll
    for (int nt = 0; nt < 4; ++nt) {
      const int np = wn * 16 + nt * 4 + (lid & 3);
      sH[m * 72 + np] =
          __float2bfloat16(fmaxf(fmaxf(acc[mt][nt][0], acc[mt][nt][1]) + bias0, 0.f));
      sH[(m + 8) * 72 + np] =
          __float2bfloat16(fmaxf(fmaxf(acc[mt][nt][2], acc[mt][nt][3]) + bias1, 0.f));
    }
  }
  __syncthreads();
  const size_t rowbase = (size_t)(b * 512 + g * 256 + by * 128);
  const int colbase = bx * 64;
#pragma unroll
  for (int p = 0; p < 4; ++p) {
    const int idx = t + p * 256;
    const int row = idx >> 3, ch = idx & 7;
    *(uint4*)&g_hp[(rowbase + row) * 1024 + colbase + ch * 8] =
        *(uint4*)&sH[row * 72 + ch * 8];
  }
}

// ---------------------------------------------------------------------------
// k2: scores = Hp @ P^T (K=1024) -> g_scb bf16
// 128B K-chunks (4 k16/iter), 2-stage, one sync/iter. dyn smem 73728.
// ---------------------------------------------------------------------------
__global__ __launch_bounds__(256, 2) void kgemm_scores() {
  constexpr int ITERS = 16;
  extern __shared__ __align__(16) char smem[];  // A 2x18432 | B 2x18432
  const int t = threadIdx.x, w = t >> 5, lid = t & 31;
  const int wm = w >> 2, wn = w & 3;
  const int n0 = blockIdx.x * 128;
  const int r0 = blockIdx.y * 128;
  const uint32_t sAb = (uint32_t)__cvta_generic_to_shared(smem);
  constexpr uint32_t BOFF = 36864;
  const char* Ab = (const char*)(g_hp + (size_t)r0 * 1024);
  const char* Bb = (const char*)(g_pat + (size_t)n0 * 1024);

  auto load_tile = [&](int s, int it) {
#pragma unroll
    for (int i = 0; i < 4; ++i) {
      const int idx = t + i * 256;
      const int row = idx >> 3, ch = idx & 7;
      const size_t go = (size_t)row * 2048 + it * 128 + ch * 16;
      const uint32_t so = (uint32_t)s * 18432 + row * 144 + ch * 16;
      cp_async16(sAb + so, Ab + go);
      cp_async16(sAb + BOFF + so, Bb + go);
    }
    CP_COMMIT();
  };

  float acc[4][4][4];
#pragma unroll
  for (int mt = 0; mt < 4; ++mt)
#pragma unroll
    for (int nt = 0; nt < 4; ++nt)
#pragma unroll
      for (int i = 0; i < 4; ++i) acc[mt][nt][i] = 0.f;

  load_tile(0, 0);
  const uint32_t aAddr0 = sAb + (wm * 64 + (lid & 15)) * 144 + (lid >> 4) * 16;
  const uint32_t bAddr0 = sAb + BOFF +
      (wn * 32 + ((lid >> 4) ? 8 : 0) + (lid & 7)) * 144 + ((lid >> 3) & 1) * 16;

#pragma unroll 1
  for (int it = 0; it < ITERS; ++it) {
    CP_WAIT(0);
    __syncthreads();
    if (it + 1 < ITERS) load_tile((it + 1) & 1, it + 1);
    const uint32_t sO = (uint32_t)(it & 1) * 18432;
#pragma unroll
    for (int ks = 0; ks < 4; ++ks) {
      uint32_t afr[4][4];
      uint32_t bfr[4][2];
#pragma unroll
      for (int mt = 0; mt < 4; ++mt)
        ldsm_x4(afr[mt], aAddr0 + sO + mt * 16 * 144 + ks * 32);
#pragma unroll
      for (int nt2 = 0; nt2 < 2; ++nt2) {
        uint32_t r4[4];
        ldsm_x4(r4, bAddr0 + sO + nt2 * 16 * 144 + ks * 32);
        bfr[nt2 * 2 + 0][0] = r4[0]; bfr[nt2 * 2 + 0][1] = r4[1];
        bfr[nt2 * 2 + 1][0] = r4[2]; bfr[nt2 * 2 + 1][1] = r4[3];
      }
#pragma unroll
      for (int mt = 0; mt < 4; ++mt)
#pragma unroll
        for (int nt = 0; nt < 4; ++nt)
          mma_16816(acc[mt][nt], afr[mt], bfr[nt][0], bfr[nt][1]);
    }
  }

  __nv_bfloat16* Crow = g_scb + (size_t)(r0 + wm * 64) * 512 + n0 + wn * 32;
  const int rr = lid >> 2;
  const int cc = (lid & 3) * 2;
#pragma unroll
  for (int mt = 0; mt < 4; ++mt)
#pragma unroll
    for (int nt = 0; nt < 4; ++nt) {
      *(uint32_t*)&Crow[(size_t)(mt * 16 + rr) * 512 + nt * 8 + cc] =
          pack_bf16(acc[mt][nt][0], acc[mt][nt][1]);
      *(uint32_t*)&Crow[(size_t)(mt * 16 + rr + 8) * 512 + nt * 8 + cc] =
          pack_bf16(acc[mt][nt][2], acc[mt][nt][3]);
    }
}

// ---------------------------------------------------------------------------
// k3: softmax over m=512 — warp per row, bf16 in/out
// ---------------------------------------------------------------------------
__global__ __launch_bounds__(256) void k3_softmax() {
  const int wid = threadIdx.x >> 5, lane = threadIdx.x & 31;
  const size_t row = (size_t)blockIdx.x * 8 + wid;
  const uint4* rp = (const uint4*)(g_scb + row * 512);
  const uint4 q0 = rp[lane];
  const uint4 q1 = rp[lane + 32];

  float f[16];
  {
    const uint32_t us[8] = {q0.x, q0.y, q0.z, q0.w, q1.x, q1.y, q1.z, q1.w};
#pragma unroll
    for (int i = 0; i < 8; ++i) {
      const __nv_bfloat162 p = *(const __nv_bfloat162*)&us[i];
      f[2 * i] = __bfloat162float(p.x);
      f[2 * i + 1] = __bfloat162float(p.y);
    }
  }
  float m = f[0];
#pragma unroll
  for (int i = 1; i < 16; ++i) m = fmaxf(m, f[i]);
#pragma unroll
  for (int o = 16; o; o >>= 1) m = fmaxf(m, __shfl_xor_sync(0xffffffffu, m, o));
  float s = 0.f;
#pragma unroll
  for (int i = 0; i < 16; ++i) {
    f[i] = __expf(f[i] - m);
    s += f[i];
  }
#pragma unroll
  for (int o = 16; o; o >>= 1) s += __shfl_xor_sync(0xffffffffu, s, o);
  const float inv = 1.f / s;

  uint4 o0, o1;
  o0.x = pack_bf16(f[0] * inv, f[1] * inv);
  o0.y = pack_bf16(f[2] * inv, f[3] * inv);
  o0.z = pack_bf16(f[4] * inv, f[5] * inv);
  o0.w = pack_bf16(f[6] * inv, f[7] * inv);
  o1.x = pack_bf16(f[8] * inv, f[9] * inv);
  o1.y = pack_bf16(f[10] * inv, f[11] * inv);
  o1.z = pack_bf16(f[12] * inv, f[13] * inv);
  o1.w = pack_bf16(f[14] * inv, f[15] * inv);
  uint4* op = (uint4*)(g_at + row * 512);
  op[lane] = o0;
  op[lane + 32] = o1;
}

// ---------------------------------------------------------------------------
// k4: retrieval = Attn @ P (K=512) -> g_hrT bf16 transposed
// 128B K-chunks (4 k16/iter), 2-stage, one sync/iter. B trans from g_pat.
// dyn smem 71680.
// ---------------------------------------------------------------------------
__global__ __launch_bounds__(256, 2) void kgemm_retrieve() {
  constexpr int ITERS = 8;
  extern __shared__ __align__(16) char smem[];  // A 2x18432 | B 2x17408
  const int t = threadIdx.x, w = t >> 5, lid = t & 31;
  const int wm = w >> 2, wn = w & 3;
  const int n0 = blockIdx.x * 128;  // lp
  const int r0 = blockIdx.y * 128;  // attn row
  const uint32_t sAb = (uint32_t)__cvta_generic_to_shared(smem);
  constexpr uint32_t BOFF = 36864;
  const char* Ab = (const char*)(g_at + (size_t)r0 * 512);
  const char* Bb = (const char*)(g_pat + n0);

  auto load_tile = [&](int s, int it) {
#pragma unroll
    for (int i = 0; i < 4; ++i) {  // A: 128 rows x 128B
      const int idx = t + i * 256;
      const int row = idx >> 3, ch = idx & 7;
      cp_async16(sAb + s * 18432 + row * 144 + ch * 16,
                 Ab + (size_t)row * 1024 + it * 128 + ch * 16);
    }
#pragma unroll
    for (int i = 0; i < 4; ++i) {  // B: 64 m-rows x 256B
      const int idx = t + i * 256;
      const int row = idx >> 4, ch = idx & 15;
      cp_async16(sAb + BOFF + s * 17408 + row * 272 + ch * 16,
                 Bb + (size_t)(it * 64 + row) * 2048 + ch * 16);
    }
    CP_COMMIT();
  };

  float acc[4][4][4];
#pragma unroll
  for (int mt = 0; mt < 4; ++mt)
#pragma unroll
    for (int nt = 0; nt < 4; ++nt)
#pragma unroll
      for (int i = 0; i < 4; ++i) acc[mt][nt][i] = 0.f;

  load_tile(0, 0);
  const uint32_t aAddr0 = sAb + (wm * 64 + (lid & 15)) * 144 + (lid >> 4) * 16;
  const uint32_t bAddr0 = sAb + BOFF +
      (((lid >> 3) & 1) * 8 + (lid & 7)) * 272 + (wn * 32 + (lid >> 4) * 8) * 2;

#pragma unroll 1
  for (int it = 0; it < ITERS; ++it) {
    CP_WAIT(0);
    __syncthreads();
    if (it + 1 < ITERS) load_tile((it + 1) & 1, it + 1);
    const uint32_t sOA = (uint32_t)(it & 1) * 18432;
    const uint32_t sOB = (uint32_t)(it & 1) * 17408;
#pragma unroll
    for (int ks = 0; ks < 4; ++ks) {
      uint32_t afr[4][4];
      uint32_t bfr[4][2];
#pragma unroll
      for (int mt = 0; mt < 4; ++mt)
        ldsm_x4(afr[mt], aAddr0 + sOA + mt * 16 * 144 + ks * 32);
#pragma unroll
      for (int nt2 = 0; nt2 < 2; ++nt2) {
        uint32_t r4[4];
        ldsm_x4_t(r4, bAddr0 + sOB + ks * 16 * 272 + nt2 * 32);
        bfr[nt2 * 2 + 0][0] = r4[0]; bfr[nt2 * 2 + 0][1] = r4[1];
        bfr[nt2 * 2 + 1][0] = r4[2]; bfr[nt2 * 2 + 1][1] = r4[3];
      }
#pragma unroll
      for (int mt = 0; mt < 4; ++mt)
#pragma unroll
        for (int nt = 0; nt < 4; ++nt)
          mma_16816(acc[mt][nt], afr[mt], bfr[nt][0], bfr[nt][1]);
    }
  }
  __syncthreads();

  __nv_bfloat16* sT = (__nv_bfloat16*)smem;  // [128 l][136 c]
#pragma unroll
  for (int mt = 0; mt < 4; ++mt) {
    const int m = wm * 64 + mt * 16 + (lid >> 2);
#pragma unroll
    for (int nt = 0; nt < 4; ++nt) {
      const int n = wn * 32 + nt * 8 + (lid & 3) * 2;
      sT[n * 136 + m] = __float2bfloat16(acc[mt][nt][0]);
      sT[(n + 1) * 136 + m] = __float2bfloat16(acc[mt][nt][1]);
      sT[n * 136 + m + 8] = __float2bfloat16(acc[mt][nt][2]);
      sT[(n + 1) * 136 + m + 8] = __float2bfloat16(acc[mt][nt][3]);
    }
  }
  __syncthreads();
  const int b = r0 >> 9;
  const int c0b = r0 & 511;
#pragma unroll
  for (int p = 0; p < 8; ++p) {
    const int idx = t + p * 256;
    const int row = idx >> 4, ch = idx & 15;
    *(uint4*)&g_hrT[((size_t)b * 1024 + n0 + row) * 512 + c0b + ch * 8] =
        *(uint4*)&sT[row * 136 + ch * 8];
  }
}

// ---------------------------------------------------------------------------
// k5: grouped ConvT(k=2,s=2) + bias + ReLU + residual
// 128B K-chunks (4 k16/iter), 2-stage, one sync/iter. dyn smem 73728.
// ---------------------------------------------------------------------------
__global__ __launch_bounds__(256, 2) void k5_hmma(
    const float* __restrict__ x, const float* __restrict__ bT,
    const float* __restrict__ rzp, float* __restrict__ out) {
  constexpr int ITERS = 4;
  extern __shared__ __align__(16) char smem[];  // A 2x18432 | B 2x18432
  const int t = threadIdx.x, w = t >> 5, lid = t & 31;
  const int wm = w >> 2, wn = w & 3;
  const int bx = blockIdx.x, by = blockIdx.y, bz = blockIdx.z;
  const int b = bz >> 1, g = bz & 1;
  const uint32_t sAb = (uint32_t)__cvta_generic_to_shared(smem);
  constexpr uint32_t BOFF = 36864;
  const char* Ab =
      (const char*)(g_hrT + ((size_t)b * 1024 + by * 128) * 512 + g * 256);
  const char* Bb = (const char*)(g_wTt + (size_t)g * 65536 + (size_t)bx * 128 * 256);

  auto load_tile = [&](int s, int it) {
#pragma unroll
    for (int i = 0; i < 4; ++i) {
      const int idx = t + i * 256;
      const int row = idx >> 3, ch = idx & 7;
      const uint32_t so = (uint32_t)s * 18432 + row * 144 + ch * 16;
      cp_async16(sAb + so, Ab + (size_t)row * 1024 + it * 128 + ch * 16);
      cp_async16(sAb + BOFF + so, Bb + (size_t)row * 512 + it * 128 + ch * 16);
    }
    CP_COMMIT();
  };

  float acc[4][4][4];
#pragma unroll
  for (int mt = 0; mt < 4; ++mt)
#pragma unroll
    for (int nt = 0; nt < 4; ++nt)
#pragma unroll
      for (int i = 0; i < 4; ++i) acc[mt][nt][i] = 0.f;

  load_tile(0, 0);
  const uint32_t aAddr0 = sAb + (wm * 64 + (lid & 15)) * 144 + (lid >> 4) * 16;
  const uint32_t bAddr0 = sAb + BOFF +
      (wn * 32 + ((lid >> 4) ? 8 : 0) + (lid & 7)) * 144 + ((lid >> 3) & 1) * 16;

#pragma unroll 1
  for (int it = 0; it < ITERS; ++it) {
    CP_WAIT(0);
    __syncthreads();
    if (it + 1 < ITERS) load_tile((it + 1) & 1, it + 1);
    const uint32_t sO = (uint32_t)(it & 1) * 18432;
#pragma unroll
    for (int ks = 0; ks < 4; ++ks) {
      uint32_t afr[4][4];
      uint32_t bfr[4][2];
#pragma unroll
      for (int mt = 0; mt < 4; ++mt)
        ldsm_x4(afr[mt], aAddr0 + sO + mt * 16 * 144 + ks * 32);
#pragma unroll
      for (int nt2 = 0; nt2 < 2; ++nt2) {
        uint32_t r4[4];
        ldsm_x4(r4, bAddr0 + sO + nt2 * 16 * 144 + ks * 32);
        bfr[nt2 * 2 + 0][0] = r4[0]; bfr[nt2 * 2 + 0][1] = r4[1];
        bfr[nt2 * 2 + 1][0] = r4[2]; bfr[nt2 * 2 + 1][1] = r4[3];
      }
#pragma unroll
      for (int mt = 0; mt < 4; ++mt)
#pragma unroll
        for (int nt = 0; nt < 4; ++nt)
          mma_16816(acc[mt][nt], afr[mt], bfr[nt][0], bfr[nt][1]);
    }
  }
  __syncthreads();

  // epilogue: bias + relu -> bf16 stage y[co 64][l 268]; then residual write
  __nv_bfloat16* sY = (__nv_bfloat16*)smem;
  float biasv[4];
#pragma unroll
  for (int nt = 0; nt < 4; ++nt) {
    const int co_l = wn * 16 + nt * 4 + (lid & 3);
    biasv[nt] = bT[g * 128 + bx * 64 + co_l];
  }
#pragma unroll
  for (int mt = 0; mt < 4; ++mt) {
    const int m = wm * 64 + mt * 16 + (lid >> 2);
#pragma unroll
    for (int nt = 0; nt < 4; ++nt) {
      const int co_l = wn * 16 + nt * 4 + (lid & 3);
      __nv_bfloat162 p0 = __floats2bfloat162_rn(
          fmaxf(acc[mt][nt][0] + biasv[nt], 0.f),
          fmaxf(acc[mt][nt][1] + biasv[nt], 0.f));
      __nv_bfloat162 p1 = __floats2bfloat162_rn(
          fmaxf(acc[mt][nt][2] + biasv[nt], 0.f),
          fmaxf(acc[mt][nt][3] + biasv[nt], 0.f));
      *(__nv_bfloat162*)&sY[co_l * 268 + 2 * m] = p0;
      *(__nv_bfloat162*)&sY[co_l * 268 + 2 * (m + 8)] = p1;
    }
  }
  __syncthreads();
  const float rz = rzp[0];
  const int co_r = t >> 2;
  const int colb = (t & 3) * 4;
  const int cog = g * 128 + bx * 64 + co_r;
  const size_t rowoff = ((size_t)b * 256 + cog) * 2048 + by * 256;
#pragma unroll
  for (int j = 0; j < 16; ++j) {
    const int col = colb + j * 16;
    const uint32_t* yp = (const uint32_t*)&sY[co_r * 268 + col];
    __nv_bfloat162 y0 = *(const __nv_bfloat162*)&yp[0];
    __nv_bfloat162 y1 = *(const __nv_bfloat162*)&yp[1];
    const float4 xv = *(const float4*)(x + rowoff + col);
    float4 o4;
    o4.x = xv.x + rz * __bfloat162float(y0.x);
    o4.y = xv.y + rz * __bfloat162float(y0.y);
    o4.z = xv.z + rz * __bfloat162float(y1.x);
    o4.w = xv.w + rz * __bfloat162float(y1.y);
    *(float4*)(out + rowoff + col) = o4;
  }
}

// ---------------------------------------------------------------------------
extern "C" void kernel_launch(void* const* d_in, const int* in_sizes, int n_in,
                              void* d_out, int out_size) {
  (void)in_sizes; (void)n_in; (void)out_size;
  const float* x        = (const float*)d_in[0];
  const float* w1       = (const float*)d_in[1];
  const float* b1       = (const float*)d_in[2];
  const float* patterns = (const float*)d_in[3];
  const float* wT       = (const float*)d_in[4];
  const float* bT       = (const float*)d_in[5];
  const float* RZ       = (const float*)d_in[6];
  float* out            = (float*)d_out;

  cudaFuncSetAttribute(kgemm_scores,
                       cudaFuncAttributeMaxDynamicSharedMemorySize, 73728);
  cudaFuncSetAttribute(kgemm_retrieve,
                       cudaFuncAttributeMaxDynamicSharedMemorySize, 71680);
  cudaFuncSetAttribute(k5_hmma,
                       cudaFuncAttributeMaxDynamicSharedMemorySize, 73728);

  kprep_all<<<608, 256>>>(w1, wT, patterns);
  k1_hmma<<<dim3(16, 2, 32), 256>>>(x, b1);
  kgemm_scores<<<dim3(4, 64), 256, 73728>>>();
  k3_softmax<<<kRows / 8, 256>>>();
  kgemm_retrieve<<<dim3(8, 64), 256, 71680>>>();
  k5_hmma<<<dim3(2, 8, 32), 256, 73728>>>(x, bT, RZ, out);
}